// round 16
// baseline (speedup 1.0000x reference)
#include <cuda_runtime.h>
#include <cstdint>

#define T_STEPS 512
#define BD 64
#define ID 256
#define HD 1024
#define OD 256
#define NG 4096
#define KD 1280
#define NPC 32
#define NCTA 136
#define NCHUNK 20                       // K chunks of 64 cols (8 k8-slices each)
#define NKI 160                         // KD / 8
#define NSTAGE 4
#define NTHREADS 288                    // 8 compute warps + 1 producer warp

#define SW_BYTES (NKI * 2 * 32 * 4 * 4) // 163840 (W fragments)
#define SO_MBAR  SW_BYTES               // 4 x (full 8B + empty 8B)
#define SO_STAGE (SW_BYTES + 1024)      // 4 x 16KB stage buffers
#define STAGE_BYTES 16384
#define SMEM_BYTES (SO_STAGE + NSTAGE * STAGE_BYTES)   // 230400
#define RED_PITCH 17

// Persistent device scratch. x/h in SLICE-MAJOR layout:
//   g_xr: [T][32 slices][64 rows][8]   (slice = k8-group of x, pair-packed within 8)
//   g_h:  [2][128 slices][64 rows][8]  (slice = 8 hidden units, pair-packed)
__device__ float g_xr[(size_t)T_STEPS * BD * ID];
__device__ float g_h[2][BD * HD];
__device__ unsigned g_arrive;

__device__ __forceinline__ uint32_t f2tf(float f) {
    uint32_t u;
    asm("cvt.rna.tf32.f32 %0, %1;" : "=r"(u) : "f"(f));
    return u;
}
__device__ __forceinline__ float f2tff(float f) { return __uint_as_float(f2tf(f)); }

// ---------------------------------------------------------------------------
__global__ void prep_kernel(const float* __restrict__ x)
{
    const size_t S_X = (size_t)T_STEPS * BD * ID;
    const size_t S_H = S_X + 2 * BD * HD;
    for (size_t i = (size_t)blockIdx.x * blockDim.x + threadIdx.x; i < S_H;
         i += (size_t)gridDim.x * blockDim.x) {
        if (i == 0) g_arrive = 0;
        if (i < S_X) {
            int c = (int)(i & 255);             // ID == 256
            int b = (int)((i >> 8) & 63);
            size_t t = i >> 14;
            int cg = c & 7;
            g_xr[((t * 32 + (c >> 3)) * 64 + b) * 8 + 2 * (cg & 3) + (cg >> 2)] =
                f2tff(x[i]);
        } else {
            ((float*)g_h)[i - S_X] = 0.0f;
        }
    }
}

// ---------------------------------------------------------------------------
// Persistent LSTM. 136 CTAs x 288 threads (8 compute warps + 1 producer).
// CTA b: gate rows [32b,32b+32) (r = 4*j+gate) or output rows (b>=128).
// R14 pipeline (producer warp, full/empty mbarriers, no block syncs in the
// mainloop) PLUS: the 4 x-only chunks of step t+1 are computed INSIDE the
// grid-barrier window (arrive -> compute x chunks -> spin-wait), shrinking
// the post-barrier serial mainloop to 16 h-chunks. Out-CTAs skip x chunks
// entirely (their W is identically 0 over k<256).
// ---------------------------------------------------------------------------
__global__ void __launch_bounds__(NTHREADS, 1) lstm_kernel(
    const float* __restrict__ W_ih, const float* __restrict__ W_hh,
    const float* __restrict__ b_ih, const float* __restrict__ b_hh,
    const float* __restrict__ W_out, const float* __restrict__ b_out,
    float* __restrict__ out)
{
    extern __shared__ __align__(1024) char smc[];
    float* sW = (float*)smc;                       // [NKI][2][32 lanes][4]
    float* sRed = (float*)(smc + SO_STAGE);        // epilogue reuse of stage area
    const uint32_t sb = (uint32_t)__cvta_generic_to_shared(smc);

    const int tid = threadIdx.x;
    const int lane = tid & 31, w = tid >> 5;
    const int G = lane >> 2, tg = lane & 3;
    const int n0 = blockIdx.x * NPC;
    const bool is_out = (n0 >= NG);
    const bool is_prod = (w == 8 && lane == 0);

    // ---- Build W fragments in smem (once, compute warps only). ----
    if (tid < 256) {
        const int r = tid >> 3;                 // local row 0..31
        const int cth = tid & 7;
        const int rowg = n0 + r;
        const int nt = r >> 3, Gr = r & 7;
#pragma unroll 1
        for (int u = 0; u < KD / 32; u++) {
            int col0 = cth * 4 + u * 32;
            float4 v;
            if (rowg < NG) {
                int orig = (rowg & 3) * HD + (rowg >> 2);   // PyTorch i,f,g,o blocks
                if (col0 < ID) v = *(const float4*)&W_ih[(size_t)orig * ID + col0];
                else           v = *(const float4*)&W_hh[(size_t)orig * HD + (col0 - ID)];
            } else {
                if (col0 < ID) v = make_float4(0.f, 0.f, 0.f, 0.f);
                else           v = *(const float4*)&W_out[(size_t)(rowg - NG) * HD + (col0 - ID)];
            }
            float vv[4] = {v.x, v.y, v.z, v.w};
#pragma unroll
            for (int e = 0; e < 4; e++) {
                int col = col0 + e;
                int ki = col >> 3, cw = col & 7;
                int tgc = cw & 3, half = cw >> 2;
                int idx = ((ki * 2 + (nt >> 1)) * 32 + (Gr * 4 + tgc)) * 4 + (nt & 1) * 2 + half;
                sW[idx] = f2tff(vv[e]);
            }
        }
    }

    // ---- Per-thread epilogue bias (threads < 256): cols 4u+g ----
    float bias[2][4];
#pragma unroll
    for (int hn = 0; hn < 2; hn++) {
#pragma unroll
        for (int g = 0; g < 4; g++) {
            int rr = n0 + hn * 16 + 4 * (tid & 3) + g;
            float bv;
            if (rr < NG) {
                int orig = (rr & 3) * HD + (rr >> 2);
                bv = b_ih[orig] + b_hh[orig];
            } else bv = b_out[rr - NG];
            bias[hn][g] = bv;
        }
    }
    float cstate[2] = {0.0f, 0.0f};

    // full[b] at SO_MBAR+16b, empty[b] at SO_MBAR+16b+8
    if (tid == 0) {
#pragma unroll
        for (int s = 0; s < NSTAGE; s++) {
            asm volatile("mbarrier.init.shared.b64 [%0], 1;"
                         :: "r"(sb + SO_MBAR + 16 * s) : "memory");
            asm volatile("mbarrier.init.shared.b64 [%0], 8;"
                         :: "r"(sb + SO_MBAR + 16 * s + 8) : "memory");
        }
    }
    __syncthreads();
    // Prime empty barriers (phase 0 completes -> first empty-wait passes)
    if (w < 8 && lane == 0) {
#pragma unroll
        for (int s = 0; s < NSTAGE; s++)
            asm volatile("mbarrier.arrive.shared.b64 _, [%0];"
                         :: "r"(sb + SO_MBAR + 16 * s + 8) : "memory");
    }
    __syncthreads();

    int pf[NSTAGE] = {0, 0, 0, 0};     // consumer: full parity per buffer
    int ep[NSTAGE] = {0, 0, 0, 0};     // producer: empty parity per buffer

    auto issue = [&](int c, int tx, const float* __restrict__ hsrc) {
        const int b = c % NSTAGE;
        {
            uint32_t m = sb + SO_MBAR + (uint32_t)(16 * b + 8);
            asm volatile(
                "{\n\t.reg .pred P;\n\tW_%=:\n\t"
                "mbarrier.try_wait.parity.shared.b64 P, [%0], %1;\n\t"
                "@P bra.uni D_%=;\n\tbra.uni W_%=;\n\tD_%=:\n\t}"
                :: "r"(m), "r"((uint32_t)ep[b]) : "memory");
            ep[b] ^= 1;
        }
        uint32_t dst = sb + SO_STAGE + (uint32_t)(b * STAGE_BYTES);
        uint32_t m   = sb + SO_MBAR + (uint32_t)(16 * b);
        const float* src = (c < 4)
            ? &g_xr[((size_t)tx * 32 + c * 8) * 512]
            : &hsrc[(size_t)(c * 8 - 32) * 512];
        asm volatile("mbarrier.arrive.expect_tx.shared.b64 _, [%0], %1;"
                     :: "r"(m), "r"((uint32_t)STAGE_BYTES) : "memory");
        asm volatile(
            "cp.async.bulk.shared::cluster.global.mbarrier::complete_tx::bytes "
            "[%0], [%1], %2, [%3];"
            :: "r"(dst), "l"(src), "r"((uint32_t)STAGE_BYTES), "r"(m) : "memory");
    };
    auto fwait = [&](int b) {
        uint32_t m = sb + SO_MBAR + (uint32_t)(16 * b);
        asm volatile(
            "{\n\t.reg .pred P;\n\tW_%=:\n\t"
            "mbarrier.try_wait.parity.shared.b64 P, [%0], %1;\n\t"
            "@P bra.uni D_%=;\n\tbra.uni W_%=;\n\tD_%=:\n\t}"
            :: "r"(m), "r"((uint32_t)pf[b]) : "memory");
        pf[b] ^= 1;
    };

    float acc[4][4][4];                 // step-persistent accumulators
#pragma unroll
    for (int m = 0; m < 4; m++)
#pragma unroll
        for (int n = 0; n < 4; n++)
#pragma unroll
            for (int e = 0; e < 4; e++) acc[m][n][e] = 0.0f;

#define MMA1(ACC, B0R, B1R)                                                     \
    asm volatile(                                                               \
        "mma.sync.aligned.m16n8k8.row.col.f32.tf32.tf32.f32 "                   \
        "{%0,%1,%2,%3},{%4,%5,%6,%7},{%8,%9},{%0,%1,%2,%3};"                    \
        : "+f"(acc[m][(ACC)][0]), "+f"(acc[m][(ACC)][1]),                       \
          "+f"(acc[m][(ACC)][2]), "+f"(acc[m][(ACC)][3])                        \
        : "r"(a0), "r"(a1), "r"(a2), "r"(a3), "r"(B0R), "r"(B1R))

    // One chunk of consumer compute on buffer c%NSTAGE
    auto consume = [&](int c) {
        fwait(c % NSTAGE);
        const float* buf = (const float*)(smc + SO_STAGE + (c % NSTAGE) * STAGE_BYTES)
                           + w * 512;
        const int kiG = c * 8 + w;
        float4 B0 = *(const float4*)&sW[((kiG * 2 + 0) * 32 + lane) * 4];
        float4 B1 = *(const float4*)&sW[((kiG * 2 + 1) * 32 + lane) * 4];
#pragma unroll
        for (int m = 0; m < 4; m++) {
            float2 aL = *(const float2*)&buf[(16 * m + G) * 8 + 2 * tg];
            float2 aH = *(const float2*)&buf[(16 * m + G + 8) * 8 + 2 * tg];
            uint32_t a0 = __float_as_uint(aL.x), a2 = __float_as_uint(aL.y);
            uint32_t a1 = __float_as_uint(aH.x), a3 = __float_as_uint(aH.y);
            MMA1(0, __float_as_uint(B0.x), __float_as_uint(B0.y));
            MMA1(1, __float_as_uint(B0.z), __float_as_uint(B0.w));
            MMA1(2, __float_as_uint(B1.x), __float_as_uint(B1.y));
            MMA1(3, __float_as_uint(B1.z), __float_as_uint(B1.w));
        }
        __syncwarp();
        if (lane == 0)
            asm volatile("mbarrier.arrive.shared.b64 _, [%0];"
                         :: "r"(sb + SO_MBAR + (uint32_t)(16 * (c % NSTAGE) + 8))
                         : "memory");
    };

    // ---- Step-0 x phase (gate CTAs only; out-CTAs skip x chunks always) ----
    if (!is_out) {
        if (is_prod) {
            asm volatile("fence.proxy.async;" ::: "memory");
            issue(0, 0, g_h[0]); issue(1, 0, g_h[0]);
            issue(2, 0, g_h[0]); issue(3, 0, g_h[0]);
        }
        if (w < 8)
            for (int c = 0; c < 4; c++) consume(c);
    }

    // ---- Time loop ----
    for (int t = 0; t <= T_STEPS; t++) {
        const bool active = is_out ? (t > 0) : (t < T_STEPS);
        if (active) {
            const float* __restrict__ hsrc = g_h[t & 1];

            // ---- mainloop: h chunks 4..19 only ----
            if (w < 8) {
#pragma unroll 1
                for (int c = 4; c < NCHUNK; c++) consume(c);
            } else if (is_prod) {
#pragma unroll 1
                for (int c = 4; c < NCHUNK; c++) issue(c, t, hsrc);
            }
            __syncthreads();    // converge: all buffers consumed, producer done

            // ---- 8-way reduction + epilogue, two N-halves of 16 cols ----
            const int b = tid >> 2, u = tid & 3;
#pragma unroll 1
            for (int hn = 0; hn < 2; hn++) {
                if (w < 8) {
#pragma unroll
                    for (int m = 0; m < 4; m++)
#pragma unroll
                        for (int nl = 0; nl < 2; nl++)
#pragma unroll
                            for (int e = 0; e < 4; e++) {
                                int row = 16 * m + G + (e >> 1) * 8;
                                int ch = nl * 8 + 2 * tg + (e & 1);
                                sRed[(w * BD + row) * RED_PITCH + ch] = acc[m][2 * hn + nl][e];
                            }
                }
                __syncthreads();
                if (tid < 256) {
                    float gv[4];
#pragma unroll
                    for (int g = 0; g < 4; g++) {
                        float s = 0.0f;
#pragma unroll
                        for (int ww = 0; ww < 8; ww++)
                            s += sRed[(ww * BD + b) * RED_PITCH + 4 * u + g];
                        gv[g] = s + bias[hn][g];
                    }
                    if (!is_out) {
                        float ig = 1.0f / (1.0f + __expf(-gv[0]));
                        float fg = 1.0f / (1.0f + __expf(-gv[1]));
                        float gg = tanhf(gv[2]);
                        float og = 1.0f / (1.0f + __expf(-gv[3]));
                        float cv = fg * cstate[hn] + ig * gg;
                        cstate[hn] = cv;
                        int jl = 4 * hn + u;
                        g_h[(t + 1) & 1][((size_t)blockIdx.x * 64 + b) * 8 +
                                         2 * (jl & 3) + (jl >> 2)] =
                            f2tff(og * tanhf(cv));
                    } else {
                        float* __restrict__ dst = out + (size_t)(t - 1) * BD * OD;
                        int col = (n0 - NG) + hn * 16 + 4 * u;
                        *(float4*)&dst[(size_t)b * OD + col] =
                            make_float4(gv[0], gv[1], gv[2], gv[3]);
                    }
                }
                __syncthreads();
            }
            // re-zero accumulators for next step
#pragma unroll
            for (int m = 0; m < 4; m++)
#pragma unroll
                for (int n = 0; n < 4; n++)
#pragma unroll
                    for (int e = 0; e < 4; e++) acc[m][n][e] = 0.0f;
        }

        if (t == T_STEPS) break;

        // ---- barrier window: arrive, compute next step's x chunks, wait ----
        const bool pre = !is_out && (t + 1 < T_STEPS);
        if (pre && is_prod) {
            asm volatile("fence.proxy.async;" ::: "memory");  // order sRed reads before bulk overwrite
            issue(0, t + 1, g_h[0]); issue(1, t + 1, g_h[0]);
            issue(2, t + 1, g_h[0]); issue(3, t + 1, g_h[0]);
        }
        __syncthreads();                     // h stores + epilogue reads done CTA-wide
        if (tid == 0) {
            __threadfence();
            atomicAdd(&g_arrive, 1u);        // ARRIVE (release)
        }
        if (pre && w < 8)
            for (int c = 0; c < 4; c++) consume(c);   // overlap with barrier skew
        if (tid == 0) {
            const unsigned target = (unsigned)(t + 1) * NCTA;
            unsigned v;
            do {
                asm volatile("ld.acquire.gpu.u32 %0, [%1];" : "=r"(v) : "l"(&g_arrive));
            } while (v < target);            // WAIT (acquire)
        }
        __syncthreads();
    }
#undef MMA1
}

// ---------------------------------------------------------------------------
extern "C" void kernel_launch(void* const* d_in, const int* in_sizes, int n_in,
                              void* d_out, int out_size)
{
    const float* x     = (const float*)d_in[0];
    const float* W_ih  = (const float*)d_in[1];
    const float* W_hh  = (const float*)d_in[2];
    const float* b_ih  = (const float*)d_in[3];
    const float* b_hh  = (const float*)d_in[4];
    const float* W_out = (const float*)d_in[5];
    const float* b_out = (const float*)d_in[6];
    float* out = (float*)d_out;

    cudaFuncSetAttribute(lstm_kernel,
                         cudaFuncAttributeMaxDynamicSharedMemorySize, SMEM_BYTES);
    prep_kernel<<<1024, 256>>>(x);
    lstm_kernel<<<NCTA, NTHREADS, SMEM_BYTES>>>(W_ih, W_hh, b_ih, b_hh, W_out, b_out, out);
}

// round 17
// speedup vs baseline: 1.3820x; 1.3820x over previous
#include <cuda_runtime.h>
#include <cstdint>

#define T_STEPS 512
#define BD 64
#define ID 256
#define HD 1024
#define OD 256
#define NG 4096
#define KD 1280
#define NPC 32
#define NCTA 136
#define NCHUNK 10                       // K chunks of 128 cols (16 k8-slices each)
#define NKI 160                         // KD / 8
#define NSTAGE 2
#define NTHREADS 288                    // 8 compute warps + 1 producer warp

#define SW_BYTES (NKI * 2 * 32 * 4 * 4) // 163840 (W fragments)
#define SO_MBAR  SW_BYTES               // 2 x (full 8B + empty 8B)
#define SO_STAGE (SW_BYTES + 1024)      // 2 x 32KB stage buffers
#define STAGE_BYTES 32768
#define SMEM_BYTES (SO_STAGE + NSTAGE * STAGE_BYTES)   // 230400
#define RED_PITCH 17

// Persistent device scratch. x/h in SLICE-MAJOR layout:
//   g_xr: [T][32 slices][64 rows][8]   (slice = k8-group of x, pair-packed within 8)
//   g_h:  [2][128 slices][64 rows][8]  (slice = 8 hidden units, pair-packed)
// => any 128-col K-chunk (16 slices) is 32KB CONTIGUOUS -> one bulk copy.
__device__ float g_xr[(size_t)T_STEPS * BD * ID];
__device__ float g_h[2][BD * HD];
__device__ unsigned g_arrive;

__device__ __forceinline__ uint32_t f2tf(float f) {
    uint32_t u;
    asm("cvt.rna.tf32.f32 %0, %1;" : "=r"(u) : "f"(f));
    return u;
}
__device__ __forceinline__ float f2tff(float f) { return __uint_as_float(f2tf(f)); }

// ---------------------------------------------------------------------------
__global__ void prep_kernel(const float* __restrict__ x)
{
    const size_t S_X = (size_t)T_STEPS * BD * ID;
    const size_t S_H = S_X + 2 * BD * HD;
    for (size_t i = (size_t)blockIdx.x * blockDim.x + threadIdx.x; i < S_H;
         i += (size_t)gridDim.x * blockDim.x) {
        if (i == 0) g_arrive = 0;
        if (i < S_X) {
            int c = (int)(i & 255);             // ID == 256
            int b = (int)((i >> 8) & 63);
            size_t t = i >> 14;
            int cg = c & 7;
            g_xr[((t * 32 + (c >> 3)) * 64 + b) * 8 + 2 * (cg & 3) + (cg >> 2)] =
                f2tff(x[i]);
        } else {
            ((float*)g_h)[i - S_X] = 0.0f;
        }
    }
}

// ---------------------------------------------------------------------------
// Persistent LSTM. 136 CTAs x 288 threads (8 compute warps + 1 producer).
// CTA b: gate rows [32b,32b+32) (r = 4*j+gate) or output rows (b>=128).
// R14 pipeline with K=128 CHUNKS: 10 chunks of 32KB, 2 stage buffers, both
// pre-issued with x-chunks before the grid barrier. Each warp handles two
// k8-slices per chunk (c*16+w and c*16+8+w) -> identical K accumulation
// order as the 20-chunk champion (bitwise-identical numerics).
// ---------------------------------------------------------------------------
__global__ void __launch_bounds__(NTHREADS, 1) lstm_kernel(
    const float* __restrict__ W_ih, const float* __restrict__ W_hh,
    const float* __restrict__ b_ih, const float* __restrict__ b_hh,
    const float* __restrict__ W_out, const float* __restrict__ b_out,
    float* __restrict__ out)
{
    extern __shared__ __align__(1024) char smc[];
    float* sW = (float*)smc;                       // [NKI][2][32 lanes][4]
    float* sRed = (float*)(smc + SO_STAGE);        // epilogue reuse of stage area
    const uint32_t sb = (uint32_t)__cvta_generic_to_shared(smc);

    const int tid = threadIdx.x;
    const int lane = tid & 31, w = tid >> 5;
    const int G = lane >> 2, tg = lane & 3;
    const int n0 = blockIdx.x * NPC;
    const bool is_out = (n0 >= NG);
    const bool is_prod = (w == 8 && lane == 0);

    // ---- Build W fragments in smem (once, compute warps only). ----
    if (tid < 256) {
        const int r = tid >> 3;                 // local row 0..31
        const int cth = tid & 7;
        const int rowg = n0 + r;
        const int nt = r >> 3, Gr = r & 7;
#pragma unroll 1
        for (int u = 0; u < KD / 32; u++) {
            int col0 = cth * 4 + u * 32;
            float4 v;
            if (rowg < NG) {
                int orig = (rowg & 3) * HD + (rowg >> 2);   // PyTorch i,f,g,o blocks
                if (col0 < ID) v = *(const float4*)&W_ih[(size_t)orig * ID + col0];
                else           v = *(const float4*)&W_hh[(size_t)orig * HD + (col0 - ID)];
            } else {
                if (col0 < ID) v = make_float4(0.f, 0.f, 0.f, 0.f);
                else           v = *(const float4*)&W_out[(size_t)(rowg - NG) * HD + (col0 - ID)];
            }
            float vv[4] = {v.x, v.y, v.z, v.w};
#pragma unroll
            for (int e = 0; e < 4; e++) {
                int col = col0 + e;
                int ki = col >> 3, cw = col & 7;
                int tgc = cw & 3, half = cw >> 2;
                int idx = ((ki * 2 + (nt >> 1)) * 32 + (Gr * 4 + tgc)) * 4 + (nt & 1) * 2 + half;
                sW[idx] = f2tff(vv[e]);
            }
        }
    }

    // ---- Per-thread epilogue bias (threads < 256): cols 4u+g ----
    float bias[2][4];
#pragma unroll
    for (int hn = 0; hn < 2; hn++) {
#pragma unroll
        for (int g = 0; g < 4; g++) {
            int rr = n0 + hn * 16 + 4 * (tid & 3) + g;
            float bv;
            if (rr < NG) {
                int orig = (rr & 3) * HD + (rr >> 2);
                bv = b_ih[orig] + b_hh[orig];
            } else bv = b_out[rr - NG];
            bias[hn][g] = bv;
        }
    }
    float cstate[2] = {0.0f, 0.0f};

    // full[b] at SO_MBAR+16b, empty[b] at SO_MBAR+16b+8
    if (tid == 0) {
#pragma unroll
        for (int s = 0; s < NSTAGE; s++) {
            asm volatile("mbarrier.init.shared.b64 [%0], 1;"
                         :: "r"(sb + SO_MBAR + 16 * s) : "memory");
            asm volatile("mbarrier.init.shared.b64 [%0], 8;"
                         :: "r"(sb + SO_MBAR + 16 * s + 8) : "memory");
        }
    }
    __syncthreads();
    // Prime empty barriers (phase 0 completes -> first empty-wait passes)
    if (w < 8 && lane == 0) {
#pragma unroll
        for (int s = 0; s < NSTAGE; s++)
            asm volatile("mbarrier.arrive.shared.b64 _, [%0];"
                         :: "r"(sb + SO_MBAR + 16 * s + 8) : "memory");
    }
    __syncthreads();

    int pf[NSTAGE] = {0, 0};           // consumer: full parity per buffer
    int ep[NSTAGE] = {0, 0};           // producer: empty parity per buffer

    auto issue = [&](int c, int tx, const float* __restrict__ hsrc) {
        const int b = c % NSTAGE;
        {
            uint32_t m = sb + SO_MBAR + (uint32_t)(16 * b + 8);
            asm volatile(
                "{\n\t.reg .pred P;\n\tW_%=:\n\t"
                "mbarrier.try_wait.parity.shared.b64 P, [%0], %1;\n\t"
                "@P bra.uni D_%=;\n\tbra.uni W_%=;\n\tD_%=:\n\t}"
                :: "r"(m), "r"((uint32_t)ep[b]) : "memory");
            ep[b] ^= 1;
        }
        uint32_t dst = sb + SO_STAGE + (uint32_t)(b * STAGE_BYTES);
        uint32_t m   = sb + SO_MBAR + (uint32_t)(16 * b);
        const float* src = (c < 2)
            ? &g_xr[((size_t)tx * 32 + c * 16) * 512]
            : &hsrc[(size_t)(c * 16 - 32) * 512];
        asm volatile("mbarrier.arrive.expect_tx.shared.b64 _, [%0], %1;"
                     :: "r"(m), "r"((uint32_t)STAGE_BYTES) : "memory");
        asm volatile(
            "cp.async.bulk.shared::cluster.global.mbarrier::complete_tx::bytes "
            "[%0], [%1], %2, [%3];"
            :: "r"(dst), "l"(src), "r"((uint32_t)STAGE_BYTES), "r"(m) : "memory");
    };
    auto fwait = [&](int b) {
        uint32_t m = sb + SO_MBAR + (uint32_t)(16 * b);
        asm volatile(
            "{\n\t.reg .pred P;\n\tW_%=:\n\t"
            "mbarrier.try_wait.parity.shared.b64 P, [%0], %1;\n\t"
            "@P bra.uni D_%=;\n\tbra.uni W_%=;\n\tD_%=:\n\t}"
            :: "r"(m), "r"((uint32_t)pf[b]) : "memory");
        pf[b] ^= 1;
    };

    // Initial pre-issue for step 0 (chunks 0,1 are x-only) — gate CTAs only
    if (!is_out && is_prod) {
        asm volatile("fence.proxy.async;" ::: "memory");
        issue(0, 0, g_h[0]);
        issue(1, 0, g_h[0]);
    }

    // ---- Time loop ----
    for (int t = 0; t <= T_STEPS; t++) {
        const bool active = is_out ? (t > 0) : (t < T_STEPS);
        if (active) {
            const int tx = (t < T_STEPS) ? t : (T_STEPS - 1);  // W=0 on x-range for out rows
            const float* __restrict__ hsrc = g_h[t & 1];

            float acc[4][4][4];
#pragma unroll
            for (int m = 0; m < 4; m++)
#pragma unroll
                for (int n = 0; n < 4; n++)
#pragma unroll
                    for (int e = 0; e < 4; e++) acc[m][n][e] = 0.0f;

            if (w < 8) {
                // ---- consumer mainloop: NO block syncs ----
#pragma unroll 1
                for (int c = 0; c < NCHUNK; c++) {
                    fwait(c % NSTAGE);
                    const float* bufbase =
                        (const float*)(smc + SO_STAGE + (c % NSTAGE) * STAGE_BYTES);
#pragma unroll
                    for (int sub = 0; sub < 2; sub++) {
                        const float* buf = bufbase + (sub * 8 + w) * 512;
                        const int kiG = c * 16 + sub * 8 + w;
                        float4 B0 = *(const float4*)&sW[((kiG * 2 + 0) * 32 + lane) * 4];
                        float4 B1 = *(const float4*)&sW[((kiG * 2 + 1) * 32 + lane) * 4];
#pragma unroll
                        for (int m = 0; m < 4; m++) {
                            float2 aL = *(const float2*)&buf[(16 * m + G) * 8 + 2 * tg];
                            float2 aH = *(const float2*)&buf[(16 * m + G + 8) * 8 + 2 * tg];
                            uint32_t a0 = __float_as_uint(aL.x), a2 = __float_as_uint(aL.y);
                            uint32_t a1 = __float_as_uint(aH.x), a3 = __float_as_uint(aH.y);
#define MMA1(ACC, B0R, B1R)                                                     \
    asm volatile(                                                               \
        "mma.sync.aligned.m16n8k8.row.col.f32.tf32.tf32.f32 "                   \
        "{%0,%1,%2,%3},{%4,%5,%6,%7},{%8,%9},{%0,%1,%2,%3};"                    \
        : "+f"(ACC[0]), "+f"(ACC[1]), "+f"(ACC[2]), "+f"(ACC[3])                \
        : "r"(a0), "r"(a1), "r"(a2), "r"(a3), "r"(B0R), "r"(B1R))
                            MMA1(acc[m][0], __float_as_uint(B0.x), __float_as_uint(B0.y));
                            MMA1(acc[m][1], __float_as_uint(B0.z), __float_as_uint(B0.w));
                            MMA1(acc[m][2], __float_as_uint(B1.x), __float_as_uint(B1.y));
                            MMA1(acc[m][3], __float_as_uint(B1.z), __float_as_uint(B1.w));
#undef MMA1
                        }
                    }
                    __syncwarp();
                    if (lane == 0)                      // this warp done with buffer
                        asm volatile("mbarrier.arrive.shared.b64 _, [%0];"
                                     :: "r"(sb + SO_MBAR + (uint32_t)(16 * (c % NSTAGE) + 8))
                                     : "memory");
                }
            } else if (is_prod) {
                // ---- producer: issue chunks 2..9 (0,1 pre-issued) ----
#pragma unroll 1
                for (int c = 2; c < NCHUNK; c++)
                    issue(c, tx, hsrc);
            }
            __syncthreads();    // converge: all buffers consumed, producer done

            // ---- 8-way reduction + epilogue, two N-halves of 16 cols ----
            const int b = tid >> 2, u = tid & 3;
#pragma unroll 1
            for (int hn = 0; hn < 2; hn++) {
                if (w < 8) {
#pragma unroll
                    for (int m = 0; m < 4; m++)
#pragma unroll
                        for (int nl = 0; nl < 2; nl++)
#pragma unroll
                            for (int e = 0; e < 4; e++) {
                                int row = 16 * m + G + (e >> 1) * 8;
                                int ch = nl * 8 + 2 * tg + (e & 1);
                                sRed[(w * BD + row) * RED_PITCH + ch] = acc[m][2 * hn + nl][e];
                            }
                }
                __syncthreads();
                if (tid < 256) {
                    float gv[4];
#pragma unroll
                    for (int g = 0; g < 4; g++) {
                        float s = 0.0f;
#pragma unroll
                        for (int ww = 0; ww < 8; ww++)
                            s += sRed[(ww * BD + b) * RED_PITCH + 4 * u + g];
                        gv[g] = s + bias[hn][g];
                    }
                    if (!is_out) {
                        float ig = 1.0f / (1.0f + __expf(-gv[0]));
                        float fg = 1.0f / (1.0f + __expf(-gv[1]));
                        float gg = tanhf(gv[2]);
                        float og = 1.0f / (1.0f + __expf(-gv[3]));
                        float cv = fg * cstate[hn] + ig * gg;
                        cstate[hn] = cv;
                        int jl = 4 * hn + u;
                        g_h[(t + 1) & 1][((size_t)blockIdx.x * 64 + b) * 8 +
                                         2 * (jl & 3) + (jl >> 2)] =
                            f2tff(og * tanhf(cv));
                    } else {
                        float* __restrict__ dst = out + (size_t)(t - 1) * BD * OD;
                        int col = (n0 - NG) + hn * 16 + 4 * u;
                        *(float4*)&dst[(size_t)b * OD + col] =
                            make_float4(gv[0], gv[1], gv[2], gv[3]);
                    }
                }
                __syncthreads();
            }
        }

        if (t == T_STEPS) break;

        // ---- pre-issue next step's x-only chunks (0,1) BEFORE barrier ----
        const bool nact = is_out ? true : (t + 1 < T_STEPS);
        if (nact && is_prod) {
            int txn = (t + 1 < T_STEPS) ? (t + 1) : (T_STEPS - 1);
            asm volatile("fence.proxy.async;" ::: "memory");  // order sRed use before bulk overwrite
            issue(0, txn, g_h[0]);
            issue(1, txn, g_h[0]);
        }

        // ---- grid barrier (136 CTAs co-resident) ----
        __syncthreads();
        if (tid == 0) {
            __threadfence();
            atomicAdd(&g_arrive, 1u);
            const unsigned target = (unsigned)(t + 1) * NCTA;
            unsigned v;
            do {
                asm volatile("ld.acquire.gpu.u32 %0, [%1];" : "=r"(v) : "l"(&g_arrive));
            } while (v < target);
        }
        __syncthreads();
    }
}

// ---------------------------------------------------------------------------
extern "C" void kernel_launch(void* const* d_in, const int* in_sizes, int n_in,
                              void* d_out, int out_size)
{
    const float* x     = (const float*)d_in[0];
    const float* W_ih  = (const float*)d_in[1];
    const float* W_hh  = (const float*)d_in[2];
    const float* b_ih  = (const float*)d_in[3];
    const float* b_hh  = (const float*)d_in[4];
    const float* W_out = (const float*)d_in[5];
    const float* b_out = (const float*)d_in[6];
    float* out = (float*)d_out;

    cudaFuncSetAttribute(lstm_kernel,
                         cudaFuncAttributeMaxDynamicSharedMemorySize, SMEM_BYTES);
    prep_kernel<<<1024, 256>>>(x);
    lstm_kernel<<<NCTA, NTHREADS, SMEM_BYTES>>>(W_ih, W_hh, b_ih, b_hh, W_out, b_out, out);
}